// round 4
// baseline (speedup 1.0000x reference)
#include <cuda_runtime.h>
#include <cstdint>

// Problem constants (fixed by the reference).
#define NN 20000      // nodes
#define NE 100000     // edges
#define DD 768        // feature dim
#define NR 4          // relations

// ---------------------------------------------------------------------------
// Device scratch (no allocations allowed anywhere).
// ---------------------------------------------------------------------------
__device__ float g_H[(size_t)NR * NN * DD];   // per-relation transformed nodes
__device__ float g_XA[(size_t)NN * DD];       // layer ping buffer
__device__ float g_XB[(size_t)NN * DD];       // layer pong buffer
__device__ float g_deg[NR * NN];              // per (relation,dst) in-degree
__device__ float g_norm[NE];                  // per-edge mean weight
__device__ int   g_src[NE];                   // canonical int32 indices
__device__ int   g_dst[NE];
__device__ int   g_et[NE];
__device__ int   g_is64;                      // 1 if inputs are int64

// ---------------------------------------------------------------------------
// Index dtype detection + canonicalization.
// If edge_index is int64 (little-endian), the first NE*2 int32 words are
// [v0,0,v1,0,...]; if int32, odd words are random node ids (never all zero).
// ---------------------------------------------------------------------------
__global__ void detect_dtype_kernel(const int* __restrict__ eidx_raw) {
    __shared__ int s_or[256];
    int acc = 0;
    // sample odd positions 1,3,...,4095 (always within the int32 extent)
    for (int i = threadIdx.x; i < 2048; i += 256)
        acc |= eidx_raw[2 * i + 1];
    s_or[threadIdx.x] = acc;
    __syncthreads();
    for (int s = 128; s > 0; s >>= 1) {
        if (threadIdx.x < s) s_or[threadIdx.x] |= s_or[threadIdx.x + s];
        __syncthreads();
    }
    if (threadIdx.x == 0) g_is64 = (s_or[0] == 0) ? 1 : 0;
}

__global__ void canon_idx_kernel(const void* __restrict__ eidx_raw,
                                 const void* __restrict__ etype_raw) {
    int e = blockIdx.x * blockDim.x + threadIdx.x;
    if (e >= NE) return;
    if (g_is64) {
        const long long* ei = (const long long*)eidx_raw;
        const long long* et = (const long long*)etype_raw;
        g_src[e] = (int)ei[e];
        g_dst[e] = (int)ei[NE + e];
        g_et[e]  = (int)et[e];
    } else {
        const int* ei = (const int*)eidx_raw;
        const int* et = (const int*)etype_raw;
        g_src[e] = ei[e];
        g_dst[e] = ei[NE + e];
        g_et[e]  = et[e];
    }
}

// ---------------------------------------------------------------------------
// Degree / norm precompute (graph fixed across layers -> once per call)
// ---------------------------------------------------------------------------
__global__ void zero_deg_kernel() {
    int i = blockIdx.x * blockDim.x + threadIdx.x;
    if (i < NR * NN) g_deg[i] = 0.0f;
}

__global__ void count_deg_kernel() {
    int e = blockIdx.x * blockDim.x + threadIdx.x;
    if (e < NE)
        atomicAdd(&g_deg[g_et[e] * NN + g_dst[e]], 1.0f);
}

__global__ void compute_norm_kernel() {
    int e = blockIdx.x * blockDim.x + threadIdx.x;
    if (e < NE)
        g_norm[e] = 1.0f / fmaxf(g_deg[g_et[e] * NN + g_dst[e]], 1.0f);
}

// ---------------------------------------------------------------------------
// Fused per-layer GEMM:
//   blockIdx.z == 0 : C = A @ root + bias   (written to the layer output)
//   blockIdx.z == r : g_H[r-1] = A @ W[r-1]
// A: [M,768] row-major.  root/W[r]: [768,768] row-major ([K][Nout]).
// Classic 128x128x8 tile, 8x8 per thread, 256 threads.
// ---------------------------------------------------------------------------
#define BM 128
#define BN 128
#define BK 8
#define TM 8
#define TN 8

__global__ __launch_bounds__(256, 2)
void rgcn_gemm_kernel(const float* __restrict__ A,
                      const float* __restrict__ Wrel,   // [4,768,768]
                      const float* __restrict__ root,   // [768,768]
                      const float* __restrict__ bias,   // [768]
                      float* __restrict__ Cout,         // [M,768]
                      int M) {
    const int z = blockIdx.z;
    const float* __restrict__ B =
        (z == 0) ? root : (Wrel + (size_t)(z - 1) * DD * DD);
    float* __restrict__ C =
        (z == 0) ? Cout : (g_H + (size_t)(z - 1) * NN * DD);
    const bool add_bias = (z == 0);

    __shared__ float As[BK][BM];   // transposed A tile
    __shared__ float Bs[BK][BN];

    const int tid  = threadIdx.x;
    const int row0 = blockIdx.y * BM;
    const int col0 = blockIdx.x * BN;

    const int a_r = tid >> 1;          // 0..127
    const int a_c = (tid & 1) * 4;     // 0 or 4
    const int b_r = tid >> 5;          // 0..7
    const int b_c = (tid & 31) * 4;    // 0..124

    const int tx = tid & 15;
    const int ty = tid >> 4;

    float acc[TM][TN];
    #pragma unroll
    for (int i = 0; i < TM; i++)
        #pragma unroll
        for (int j = 0; j < TN; j++) acc[i][j] = 0.0f;

    const int ga_row = row0 + a_r;
    const bool a_ok = (ga_row < M);

    for (int k0 = 0; k0 < DD; k0 += BK) {
        float4 av = make_float4(0.f, 0.f, 0.f, 0.f);
        if (a_ok)
            av = *reinterpret_cast<const float4*>(
                A + (size_t)ga_row * DD + k0 + a_c);
        As[a_c + 0][a_r] = av.x;
        As[a_c + 1][a_r] = av.y;
        As[a_c + 2][a_r] = av.z;
        As[a_c + 3][a_r] = av.w;

        float4 bv = *reinterpret_cast<const float4*>(
            B + (size_t)(k0 + b_r) * DD + col0 + b_c);
        *reinterpret_cast<float4*>(&Bs[b_r][b_c]) = bv;

        __syncthreads();

        #pragma unroll
        for (int k = 0; k < BK; k++) {
            float ar[TM], br[TN];
            #pragma unroll
            for (int i = 0; i < TM; i++) ar[i] = As[k][ty * TM + i];
            #pragma unroll
            for (int j = 0; j < TN; j++) br[j] = Bs[k][tx * TN + j];
            #pragma unroll
            for (int i = 0; i < TM; i++)
                #pragma unroll
                for (int j = 0; j < TN; j++)
                    acc[i][j] += ar[i] * br[j];
        }
        __syncthreads();
    }

    #pragma unroll
    for (int i = 0; i < TM; i++) {
        int gr = row0 + ty * TM + i;
        if (gr >= M) continue;
        #pragma unroll
        for (int j = 0; j < TN; j += 4) {
            int gc = col0 + tx * TN + j;
            float4 v = make_float4(acc[i][j], acc[i][j + 1],
                                   acc[i][j + 2], acc[i][j + 3]);
            if (add_bias) {
                v.x += bias[gc];
                v.y += bias[gc + 1];
                v.z += bias[gc + 2];
                v.w += bias[gc + 3];
            }
            *reinterpret_cast<float4*>(C + (size_t)gr * DD + gc) = v;
        }
    }
}

// ---------------------------------------------------------------------------
// Edge scatter: out[dst] += g_H[etype][src] * norm[e]
// One block per edge, coalesced reads, float atomics into L2-resident output.
// ---------------------------------------------------------------------------
__global__ void scatter_kernel(float* __restrict__ out) {
    const int e = blockIdx.x;
    const int s = g_src[e];
    const int d = g_dst[e];
    const int r = g_et[e];
    const float w = g_norm[e];
    const float* __restrict__ h = g_H + ((size_t)r * NN + s) * DD;
    float* __restrict__ o = out + (size_t)d * DD;
    for (int j = threadIdx.x; j < DD; j += blockDim.x)
        atomicAdd(o + j, h[j] * w);
}

// ---------------------------------------------------------------------------
// ReLU (vectorized, in-place)
// ---------------------------------------------------------------------------
__global__ void relu_kernel(float* __restrict__ x) {
    const size_t n4 = (size_t)NN * DD / 4;
    size_t i = (size_t)blockIdx.x * blockDim.x + threadIdx.x;
    if (i < n4) {
        float4 v = reinterpret_cast<float4*>(x)[i];
        v.x = fmaxf(v.x, 0.f);
        v.y = fmaxf(v.y, 0.f);
        v.z = fmaxf(v.z, 0.f);
        v.w = fmaxf(v.w, 0.f);
        reinterpret_cast<float4*>(x)[i] = v;
    }
}

// ---------------------------------------------------------------------------
// Orchestration
// ---------------------------------------------------------------------------
extern "C" void kernel_launch(void* const* d_in, const int* in_sizes, int n_in,
                              void* d_out, int out_size) {
    const float* entity = (const float*)d_in[0];
    const void*  eidx   = d_in[1];
    const void*  etype  = d_in[2];
    const float* W1 = (const float*)d_in[3];
    const float* r1 = (const float*)d_in[4];
    const float* b1 = (const float*)d_in[5];
    const float* W2 = (const float*)d_in[6];
    const float* r2 = (const float*)d_in[7];
    const float* b2 = (const float*)d_in[8];
    const float* W3 = (const float*)d_in[9];
    const float* r3 = (const float*)d_in[10];
    const float* b3 = (const float*)d_in[11];

    float* XA = nullptr;
    float* XB = nullptr;
    cudaGetSymbolAddress((void**)&XA, g_XA);
    cudaGetSymbolAddress((void**)&XB, g_XB);
    float* OUT = (float*)d_out;

    // --- canonicalize indices (robust to int32 or int64 harness layout) ---
    detect_dtype_kernel<<<1, 256>>>((const int*)eidx);
    canon_idx_kernel<<<(NE + 255) / 256, 256>>>(eidx, etype);

    // --- per-edge mean weights (graph fixed across layers) ---
    zero_deg_kernel<<<(NR * NN + 255) / 256, 256>>>();
    count_deg_kernel<<<(NE + 255) / 256, 256>>>();
    compute_norm_kernel<<<(NE + 255) / 256, 256>>>();

    const dim3 gemm_grid(DD / BN, (NN + BM - 1) / BM, NR + 1);
    const int relu_grid = (int)(((size_t)NN * DD / 4 + 255) / 256);

    // --- layer 1: entity -> XA ---
    rgcn_gemm_kernel<<<gemm_grid, 256>>>(entity, W1, r1, b1, XA, NN);
    scatter_kernel<<<NE, 256>>>(XA);
    relu_kernel<<<relu_grid, 256>>>(XA);

    // --- layer 2: XA -> XB ---
    rgcn_gemm_kernel<<<gemm_grid, 256>>>(XA, W2, r2, b2, XB, NN);
    scatter_kernel<<<NE, 256>>>(XB);
    relu_kernel<<<relu_grid, 256>>>(XB);

    // --- layer 3: XB -> d_out (no ReLU) ---
    rgcn_gemm_kernel<<<gemm_grid, 256>>>(XB, W3, r3, b3, OUT, NN);
    scatter_kernel<<<NE, 256>>>(OUT);
}

// round 10
// speedup vs baseline: 3.1722x; 3.1722x over previous
#include <cuda_runtime.h>
#include <cstdint>

// Problem constants (fixed by the reference).
#define NN 20000      // nodes
#define NE 100000     // edges
#define DD 768        // feature dim
#define NR 4          // relations

// ---------------------------------------------------------------------------
// Device scratch (no allocations allowed anywhere).
// ---------------------------------------------------------------------------
__device__ float g_H[(size_t)NR * NN * DD];      // per-relation transformed nodes
__device__ float g_XA[(size_t)NN * DD];          // layer ping buffer
__device__ float g_XB[(size_t)NN * DD];          // layer pong buffer
__device__ float g_XC[(size_t)NN * DD];          // tf32-rounded entity
__device__ float g_WT[(size_t)15 * DD * DD];     // transposed tf32 weights [l*5+s][N][K]
__device__ float g_deg[NR * NN];                 // per (relation,dst) in-degree
__device__ float g_norm[NE];                     // per-edge mean weight
__device__ int   g_src[NE];
__device__ int   g_dst[NE];
__device__ int   g_et[NE];
__device__ int   g_is64;

// ---------------------------------------------------------------------------
// Helpers (base-PTX only: cp.async sm_80, mma.sync tf32 sm_80 — OK on sm_100)
// ---------------------------------------------------------------------------
__device__ __forceinline__ uint32_t smem_u32(const void* p) {
    uint32_t a;
    asm("{ .reg .u64 t; cvta.to.shared.u64 t, %1; cvt.u32.u64 %0, t; }"
        : "=r"(a) : "l"(p));
    return a;
}
__device__ __forceinline__ void cp_async16(uint32_t dst, const void* src) {
    asm volatile("cp.async.cg.shared.global [%0], [%1], 16;\n"
                 :: "r"(dst), "l"(src));
}
#define CP_COMMIT()  asm volatile("cp.async.commit_group;\n" ::: "memory")
#define CP_WAIT(n)   asm volatile("cp.async.wait_group %0;\n" :: "n"(n) : "memory")

// cvt.rna.tf32.f32 needs a .b32 destination (ptxas rejects an f32 reg).
__device__ __forceinline__ float to_tf32(float x) {
    uint32_t r;
    asm("cvt.rna.tf32.f32 %0, %1;" : "=r"(r) : "f"(x));
    return __uint_as_float(r);
}

// D += A(16x8 tf32,row) * B(8x8 tf32,col); fp32 accum.
__device__ __forceinline__ void mma16n8k8(float* c, const uint32_t* a,
                                          const uint32_t* b) {
    asm volatile(
        "mma.sync.aligned.m16n8k8.row.col.f32.tf32.tf32.f32 "
        "{%0,%1,%2,%3}, {%4,%5,%6,%7}, {%8,%9}, {%0,%1,%2,%3};"
        : "+f"(c[0]), "+f"(c[1]), "+f"(c[2]), "+f"(c[3])
        : "r"(a[0]), "r"(a[1]), "r"(a[2]), "r"(a[3]), "r"(b[0]), "r"(b[1]));
}

// ---------------------------------------------------------------------------
// Index dtype detection + canonicalization (validated in R4).
// ---------------------------------------------------------------------------
__global__ void detect_dtype_kernel(const int* __restrict__ eidx_raw) {
    __shared__ int s_or[256];
    int acc = 0;
    for (int i = threadIdx.x; i < 2048; i += 256)
        acc |= eidx_raw[2 * i + 1];
    s_or[threadIdx.x] = acc;
    __syncthreads();
    for (int s = 128; s > 0; s >>= 1) {
        if (threadIdx.x < s) s_or[threadIdx.x] |= s_or[threadIdx.x + s];
        __syncthreads();
    }
    if (threadIdx.x == 0) g_is64 = (s_or[0] == 0) ? 1 : 0;
}

__global__ void canon_idx_kernel(const void* __restrict__ eidx_raw,
                                 const void* __restrict__ etype_raw) {
    int e = blockIdx.x * blockDim.x + threadIdx.x;
    if (e >= NE) return;
    if (g_is64) {
        const long long* ei = (const long long*)eidx_raw;
        const long long* et = (const long long*)etype_raw;
        g_src[e] = (int)ei[e];
        g_dst[e] = (int)ei[NE + e];
        g_et[e]  = (int)et[e];
    } else {
        const int* ei = (const int*)eidx_raw;
        const int* et = (const int*)etype_raw;
        g_src[e] = ei[e];
        g_dst[e] = ei[NE + e];
        g_et[e]  = et[e];
    }
}

__global__ void zero_deg_kernel() {
    int i = blockIdx.x * blockDim.x + threadIdx.x;
    if (i < NR * NN) g_deg[i] = 0.0f;
}
__global__ void count_deg_kernel() {
    int e = blockIdx.x * blockDim.x + threadIdx.x;
    if (e < NE) atomicAdd(&g_deg[g_et[e] * NN + g_dst[e]], 1.0f);
}
__global__ void compute_norm_kernel() {
    int e = blockIdx.x * blockDim.x + threadIdx.x;
    if (e < NE) g_norm[e] = 1.0f / fmaxf(g_deg[g_et[e] * NN + g_dst[e]], 1.0f);
}

// ---------------------------------------------------------------------------
// Weight transpose (all 15 mats) with tf32 rounding on store.
// slot 0 = root^T, 1..4 = W[r]^T ; dst[n][k] = tf32(src[k][n]).
// ---------------------------------------------------------------------------
__global__ void transpose_all_kernel(const float* __restrict__ W1, const float* __restrict__ r1,
                                     const float* __restrict__ W2, const float* __restrict__ r2,
                                     const float* __restrict__ W3, const float* __restrict__ r3) {
    __shared__ float t[32][33];
    const int zz = blockIdx.z;
    const int layer = zz / 5, slot = zz % 5;
    const float* roots[3] = {r1, r2, r3};
    const float* Ws[3]    = {W1, W2, W3};
    const float* src = (slot == 0) ? roots[layer]
                                   : Ws[layer] + (size_t)(slot - 1) * DD * DD;
    float* dst = g_WT + (size_t)zz * DD * DD;

    int x  = blockIdx.x * 32 + threadIdx.x;
    int y0 = blockIdx.y * 32;
    for (int j = threadIdx.y; j < 32; j += 8)
        t[j][threadIdx.x] = src[(size_t)(y0 + j) * DD + x];
    __syncthreads();
    int x2  = blockIdx.y * 32 + threadIdx.x;
    int y20 = blockIdx.x * 32;
    for (int j = threadIdx.y; j < 32; j += 8)
        dst[(size_t)(y20 + j) * DD + x2] = to_tf32(t[threadIdx.x][j]);
}

// Entity -> tf32-rounded copy (GEMM A operand for layer 1).
__global__ void convert_entity_kernel(const float* __restrict__ x) {
    const size_t n4 = (size_t)NN * DD / 4;
    size_t i = (size_t)blockIdx.x * blockDim.x + threadIdx.x;
    if (i < n4) {
        float4 v = reinterpret_cast<const float4*>(x)[i];
        v.x = to_tf32(v.x); v.y = to_tf32(v.y);
        v.z = to_tf32(v.z); v.w = to_tf32(v.w);
        reinterpret_cast<float4*>(g_XC)[i] = v;
    }
}

// ---------------------------------------------------------------------------
// tf32 mma.sync GEMM.
// CTA 128x256 out, BK=32, 256 thr (8 warps), warp tile 64x64.
//   blockIdx.z = slot (0 -> root+bias into Cout, 1..4 -> g_H[slot-1]).
// SMEM rows padded to 36 floats: frag-load bank = (4*gid+tig)%32, conflict-free.
// ---------------------------------------------------------------------------
#define BM  128
#define BN  256
#define BK  32
#define PAD 36
#define ASZB (BM * PAD * 4)                 // 18432 B per A buffer
#define BSZB (BN * PAD * 4)                 // 36864 B per B buffer
#define SMTOT (2 * ASZB + 2 * BSZB)         // 110592 B

__global__ __launch_bounds__(256, 1)
void gemm_mma_kernel(const float* __restrict__ Ain,
                     const float* __restrict__ WT5,   // 5 transposed [N][K] mats
                     const float* __restrict__ bias,
                     float* __restrict__ Cout,
                     int M) {
    extern __shared__ float sm[];
    const uint32_t sb = smem_u32(sm);
    const int tid  = threadIdx.x;
    const int lane = tid & 31;
    const int wid  = tid >> 5;
    const int gid  = lane >> 2;      // 0..7
    const int tig  = lane & 3;       // 0..3
    const int wr   = wid >> 2;       // 0..1  (64-row band)
    const int wc   = wid & 3;        // 0..3  (64-col band)
    const int z    = blockIdx.z;

    const float* __restrict__ Bmat = WT5 + (size_t)z * DD * DD;
    float* __restrict__ C = (z == 0) ? Cout : (g_H + (size_t)(z - 1) * NN * DD);

    const int row0 = blockIdx.y * BM;
    const int col0 = blockIdx.x * BN;

    float acc[4][8][4];
    #pragma unroll
    for (int mt = 0; mt < 4; mt++)
        #pragma unroll
        for (int nt = 0; nt < 8; nt++)
            #pragma unroll
            for (int q = 0; q < 4; q++) acc[mt][nt][q] = 0.0f;

    // ---- async tile fill: A 1024 float4 slots, B 2048 float4 slots ----
    #define LOAD_CHUNK(c)                                                     \
    do {                                                                      \
        const int _buf = (c) & 1;                                             \
        const int _k0  = (c) * BK;                                            \
        const uint32_t _ab = sb + _buf * ASZB;                                \
        const uint32_t _bb = sb + 2 * ASZB + _buf * BSZB;                     \
        _Pragma("unroll")                                                     \
        for (int _j = 0; _j < 4; _j++) {                                      \
            int _s = tid + 256 * _j, _r = _s >> 3, _c4 = _s & 7;              \
            int _ar = row0 + _r; if (_ar >= M) _ar = M - 1;                   \
            cp_async16(_ab + (_r * PAD + _c4 * 4) * 4,                        \
                       Ain + (size_t)_ar * DD + _k0 + _c4 * 4);               \
        }                                                                     \
        _Pragma("unroll")                                                     \
        for (int _j = 0; _j < 8; _j++) {                                      \
            int _s = tid + 256 * _j, _r = _s >> 3, _c4 = _s & 7;              \
            cp_async16(_bb + (_r * PAD + _c4 * 4) * 4,                        \
                       Bmat + (size_t)(col0 + _r) * DD + _k0 + _c4 * 4);      \
        }                                                                     \
        CP_COMMIT();                                                          \
    } while (0)

    LOAD_CHUNK(0);
    for (int c = 0; c < 24; c++) {
        if (c < 23) { LOAD_CHUNK(c + 1); CP_WAIT(1); }
        else        { CP_WAIT(0); }
        __syncthreads();

        const int buf = c & 1;
        const float* __restrict__ as = sm + buf * (BM * PAD);
        const float* __restrict__ bs = sm + 2 * (BM * PAD) + buf * (BN * PAD);

        #pragma unroll
        for (int ks = 0; ks < 4; ks++) {
            const int kk = ks * 8 + tig;
            uint32_t af[4][4], bf[8][2];
            #pragma unroll
            for (int mt = 0; mt < 4; mt++) {
                int r = wr * 64 + mt * 16 + gid;
                af[mt][0] = __float_as_uint(as[r * PAD + kk]);
                af[mt][1] = __float_as_uint(as[(r + 8) * PAD + kk]);
                af[mt][2] = __float_as_uint(as[r * PAD + kk + 4]);
                af[mt][3] = __float_as_uint(as[(r + 8) * PAD + kk + 4]);
            }
            #pragma unroll
            for (int nt = 0; nt < 8; nt++) {
                int n = wc * 64 + nt * 8 + gid;
                bf[nt][0] = __float_as_uint(bs[n * PAD + kk]);
                bf[nt][1] = __float_as_uint(bs[n * PAD + kk + 4]);
            }
            #pragma unroll
            for (int mt = 0; mt < 4; mt++)
                #pragma unroll
                for (int nt = 0; nt < 8; nt++)
                    mma16n8k8(acc[mt][nt], af[mt], bf[nt]);
        }
        __syncthreads();
    }

    // ---- epilogue ----
    #pragma unroll
    for (int mt = 0; mt < 4; mt++) {
        const int r0g = row0 + wr * 64 + mt * 16 + gid;
        #pragma unroll
        for (int nt = 0; nt < 8; nt++) {
            const int col = col0 + wc * 64 + nt * 8 + 2 * tig;
            float bx = 0.f, by = 0.f;
            if (z == 0) { bx = bias[col]; by = bias[col + 1]; }
            if (r0g < M) {
                float2 v = make_float2(acc[mt][nt][0] + bx, acc[mt][nt][1] + by);
                *reinterpret_cast<float2*>(C + (size_t)r0g * DD + col) = v;
            }
            if (r0g + 8 < M) {
                float2 v = make_float2(acc[mt][nt][2] + bx, acc[mt][nt][3] + by);
                *reinterpret_cast<float2*>(C + (size_t)(r0g + 8) * DD + col) = v;
            }
        }
    }
}

// ---------------------------------------------------------------------------
// Edge scatter (validated) + ReLU-with-tf32-rounding (X feeds only next GEMM).
// ---------------------------------------------------------------------------
__global__ void scatter_kernel(float* __restrict__ out) {
    const int e = blockIdx.x;
    const int s = g_src[e];
    const int d = g_dst[e];
    const int r = g_et[e];
    const float w = g_norm[e];
    const float* __restrict__ h = g_H + ((size_t)r * NN + s) * DD;
    float* __restrict__ o = out + (size_t)d * DD;
    for (int j = threadIdx.x; j < DD; j += blockDim.x)
        atomicAdd(o + j, h[j] * w);
}

__global__ void relu_tf32_kernel(float* __restrict__ x) {
    const size_t n4 = (size_t)NN * DD / 4;
    size_t i = (size_t)blockIdx.x * blockDim.x + threadIdx.x;
    if (i < n4) {
        float4 v = reinterpret_cast<float4*>(x)[i];
        v.x = to_tf32(fmaxf(v.x, 0.f));
        v.y = to_tf32(fmaxf(v.y, 0.f));
        v.z = to_tf32(fmaxf(v.z, 0.f));
        v.w = to_tf32(fmaxf(v.w, 0.f));
        reinterpret_cast<float4*>(x)[i] = v;
    }
}

// ---------------------------------------------------------------------------
// Orchestration
// ---------------------------------------------------------------------------
extern "C" void kernel_launch(void* const* d_in, const int* in_sizes, int n_in,
                              void* d_out, int out_size) {
    const float* entity = (const float*)d_in[0];
    const void*  eidx   = d_in[1];
    const void*  etype  = d_in[2];
    const float* W1 = (const float*)d_in[3];
    const float* r1 = (const float*)d_in[4];
    const float* b1 = (const float*)d_in[5];
    const float* W2 = (const float*)d_in[6];
    const float* r2 = (const float*)d_in[7];
    const float* b2 = (const float*)d_in[8];
    const float* W3 = (const float*)d_in[9];
    const float* r3 = (const float*)d_in[10];
    const float* b3 = (const float*)d_in[11];

    float *XA = nullptr, *XB = nullptr, *XC = nullptr, *WT = nullptr;
    cudaGetSymbolAddress((void**)&XA, g_XA);
    cudaGetSymbolAddress((void**)&XB, g_XB);
    cudaGetSymbolAddress((void**)&XC, g_XC);
    cudaGetSymbolAddress((void**)&WT, g_WT);
    float* OUT = (float*)d_out;

    cudaFuncSetAttribute(gemm_mma_kernel,
                         cudaFuncAttributeMaxDynamicSharedMemorySize, SMTOT);

    const dim3 tr_grid(24, 24, 15), tr_blk(32, 8);
    const dim3 gemm_grid(DD / BN, (NN + BM - 1) / BM, NR + 1);   // (3, 157, 5)
    const int  vec_grid = (int)(((size_t)NN * DD / 4 + 255) / 256);
    const size_t WTL = (size_t)5 * DD * DD;

    // launches 0-4 (GEMM-L1 lands at index 5 for ncu -s 5)
    transpose_all_kernel<<<tr_grid, tr_blk>>>(W1, r1, W2, r2, W3, r3);
    convert_entity_kernel<<<vec_grid, 256>>>(entity);
    detect_dtype_kernel<<<1, 256>>>((const int*)eidx);
    canon_idx_kernel<<<(NE + 255) / 256, 256>>>(eidx, etype);
    zero_deg_kernel<<<(NR * NN + 255) / 256, 256>>>();

    // --- layer 1: tf32(entity) -> XA ---
    gemm_mma_kernel<<<gemm_grid, 256, SMTOT>>>(XC, WT + 0 * WTL, b1, XA, NN);
    count_deg_kernel<<<(NE + 255) / 256, 256>>>();
    compute_norm_kernel<<<(NE + 255) / 256, 256>>>();
    scatter_kernel<<<NE, 256>>>(XA);
    relu_tf32_kernel<<<vec_grid, 256>>>(XA);

    // --- layer 2: XA -> XB ---
    gemm_mma_kernel<<<gemm_grid, 256, SMTOT>>>(XA, WT + 1 * WTL, b2, XB, NN);
    scatter_kernel<<<NE, 256>>>(XB);
    relu_tf32_kernel<<<vec_grid, 256>>>(XB);

    // --- layer 3: XB -> d_out (no ReLU) ---
    gemm_mma_kernel<<<gemm_grid, 256, SMTOT>>>(XB, WT + 2 * WTL, b3, OUT, NN);
    scatter_kernel<<<NE, 256>>>(OUT);
}

// round 11
// speedup vs baseline: 4.3669x; 1.3766x over previous
#include <cuda_runtime.h>
#include <cuda_fp16.h>
#include <cstdint>

// Problem constants (fixed by the reference).
#define NN 20000      // nodes
#define NE 100000     // edges
#define DD 768        // feature dim
#define NR 4          // relations

// ---------------------------------------------------------------------------
// Device scratch (no allocations allowed anywhere).
// ---------------------------------------------------------------------------
__device__ float  g_H[(size_t)NR * NN * DD];     // per-relation transformed nodes
__device__ float  g_XA[(size_t)NN * DD];         // layer ping buffer (fp32)
__device__ float  g_XB[(size_t)NN * DD];         // layer pong buffer (fp32)
__device__ __half g_Ah[(size_t)NN * DD];         // fp16 GEMM A operand (current layer)
__device__ __half g_WTh[(size_t)15 * DD * DD];   // transposed fp16 weights [l*5+s][N][K]
__device__ float  g_deg[NR * NN];                // per (relation,dst) in-degree
__device__ float  g_norm[NE];                    // per-edge mean weight
__device__ int    g_src[NE];
__device__ int    g_dst[NE];
__device__ int    g_et[NE];
__device__ int    g_is64;

// ---------------------------------------------------------------------------
// Helpers (base-PTX only: cp.async sm_80, mma.sync fp16 — OK on sm_100 target)
// ---------------------------------------------------------------------------
__device__ __forceinline__ uint32_t smem_u32(const void* p) {
    uint32_t a;
    asm("{ .reg .u64 t; cvta.to.shared.u64 t, %1; cvt.u32.u64 %0, t; }"
        : "=r"(a) : "l"(p));
    return a;
}
__device__ __forceinline__ void cp_async16(uint32_t dst, const void* src) {
    asm volatile("cp.async.cg.shared.global [%0], [%1], 16;\n"
                 :: "r"(dst), "l"(src));
}
#define CP_COMMIT()  asm volatile("cp.async.commit_group;\n" ::: "memory")
#define CP_WAIT(n)   asm volatile("cp.async.wait_group %0;\n" :: "n"(n) : "memory")

// D += A(16x16 f16,row) * B(16x8 f16,col); fp32 accum.
__device__ __forceinline__ void mma16n8k16(float* c, const uint32_t* a,
                                           const uint32_t* b) {
    asm volatile(
        "mma.sync.aligned.m16n8k16.row.col.f32.f16.f16.f32 "
        "{%0,%1,%2,%3}, {%4,%5,%6,%7}, {%8,%9}, {%0,%1,%2,%3};"
        : "+f"(c[0]), "+f"(c[1]), "+f"(c[2]), "+f"(c[3])
        : "r"(a[0]), "r"(a[1]), "r"(a[2]), "r"(a[3]), "r"(b[0]), "r"(b[1]));
}

// ---------------------------------------------------------------------------
// Index dtype detection + canonicalization (validated in R4).
// ---------------------------------------------------------------------------
__global__ void detect_dtype_kernel(const int* __restrict__ eidx_raw) {
    __shared__ int s_or[256];
    int acc = 0;
    for (int i = threadIdx.x; i < 2048; i += 256)
        acc |= eidx_raw[2 * i + 1];
    s_or[threadIdx.x] = acc;
    __syncthreads();
    for (int s = 128; s > 0; s >>= 1) {
        if (threadIdx.x < s) s_or[threadIdx.x] |= s_or[threadIdx.x + s];
        __syncthreads();
    }
    if (threadIdx.x == 0) g_is64 = (s_or[0] == 0) ? 1 : 0;
}

__global__ void canon_idx_kernel(const void* __restrict__ eidx_raw,
                                 const void* __restrict__ etype_raw) {
    int e = blockIdx.x * blockDim.x + threadIdx.x;
    if (e >= NE) return;
    if (g_is64) {
        const long long* ei = (const long long*)eidx_raw;
        const long long* et = (const long long*)etype_raw;
        g_src[e] = (int)ei[e];
        g_dst[e] = (int)ei[NE + e];
        g_et[e]  = (int)et[e];
    } else {
        const int* ei = (const int*)eidx_raw;
        const int* et = (const int*)etype_raw;
        g_src[e] = ei[e];
        g_dst[e] = ei[NE + e];
        g_et[e]  = et[e];
    }
}

__global__ void zero_deg_kernel() {
    int i = blockIdx.x * blockDim.x + threadIdx.x;
    if (i < NR * NN) g_deg[i] = 0.0f;
}
__global__ void count_deg_kernel() {
    int e = blockIdx.x * blockDim.x + threadIdx.x;
    if (e < NE) atomicAdd(&g_deg[g_et[e] * NN + g_dst[e]], 1.0f);
}
__global__ void compute_norm_kernel() {
    int e = blockIdx.x * blockDim.x + threadIdx.x;
    if (e < NE) g_norm[e] = 1.0f / fmaxf(g_deg[g_et[e] * NN + g_dst[e]], 1.0f);
}

// ---------------------------------------------------------------------------
// Weight transpose (all 15 mats), fp16 on store.
// slot 0 = root^T, 1..4 = W[r]^T ; dst[n][k] = f16(src[k][n]).
// ---------------------------------------------------------------------------
__global__ void transpose_all_kernel(const float* __restrict__ W1, const float* __restrict__ r1,
                                     const float* __restrict__ W2, const float* __restrict__ r2,
                                     const float* __restrict__ W3, const float* __restrict__ r3) {
    __shared__ float t[32][33];
    const int zz = blockIdx.z;
    const int layer = zz / 5, slot = zz % 5;
    const float* roots[3] = {r1, r2, r3};
    const float* Ws[3]    = {W1, W2, W3};
    const float* src = (slot == 0) ? roots[layer]
                                   : Ws[layer] + (size_t)(slot - 1) * DD * DD;
    __half* dst = g_WTh + (size_t)zz * DD * DD;

    int x  = blockIdx.x * 32 + threadIdx.x;
    int y0 = blockIdx.y * 32;
    for (int j = threadIdx.y; j < 32; j += 8)
        t[j][threadIdx.x] = src[(size_t)(y0 + j) * DD + x];
    __syncthreads();
    int x2  = blockIdx.y * 32 + threadIdx.x;
    int y20 = blockIdx.x * 32;
    for (int j = threadIdx.y; j < 32; j += 8)
        dst[(size_t)(y20 + j) * DD + x2] = __float2half_rn(t[threadIdx.x][j]);
}

// Entity -> fp16 copy (GEMM A operand for layer 1).
__global__ void convert_entity_kernel(const float* __restrict__ x) {
    const size_t n4 = (size_t)NN * DD / 4;
    size_t i = (size_t)blockIdx.x * blockDim.x + threadIdx.x;
    if (i < n4) {
        float4 v = reinterpret_cast<const float4*>(x)[i];
        __half2* o = reinterpret_cast<__half2*>(g_Ah) + i * 2;
        o[0] = __floats2half2_rn(v.x, v.y);
        o[1] = __floats2half2_rn(v.z, v.w);
    }
}

// ReLU fp32 -> fp16 operand (X only feeds the next GEMM; scatter reads g_H).
__global__ void relu_to_half_kernel(const float* __restrict__ x) {
    const size_t n4 = (size_t)NN * DD / 4;
    size_t i = (size_t)blockIdx.x * blockDim.x + threadIdx.x;
    if (i < n4) {
        float4 v = reinterpret_cast<const float4*>(x)[i];
        v.x = fmaxf(v.x, 0.f); v.y = fmaxf(v.y, 0.f);
        v.z = fmaxf(v.z, 0.f); v.w = fmaxf(v.w, 0.f);
        __half2* o = reinterpret_cast<__half2*>(g_Ah) + i * 2;
        o[0] = __floats2half2_rn(v.x, v.y);
        o[1] = __floats2half2_rn(v.z, v.w);
    }
}

// ---------------------------------------------------------------------------
// fp16 mma.sync GEMM (m16n8k16), fp32 accumulate.
// CTA 128x256 out, BK=32, 256 thr (8 warps), warp tile 64x64, 3-stage cp.async.
//   blockIdx.z = slot (0 -> root+bias into Cout, 1..4 -> g_H[slot-1]).
// SMEM rows padded to 40 halfs: frag b32 bank = (gid*20+tig)%32, conflict-free.
// ---------------------------------------------------------------------------
#define BM   128
#define BN   256
#define BK   32
#define PADH 40
#define ASZB (BM * PADH * 2)                 // 10240 B per A stage
#define BSZB (BN * PADH * 2)                 // 20480 B per B stage
#define STG  3
#define SMTOT (STG * (ASZB + BSZB))          // 92160 B

__global__ __launch_bounds__(256, 1)
void gemm_mma_kernel(const __half* __restrict__ Ain,
                     const __half* __restrict__ WT5,   // 5 transposed [N][K] mats
                     const float* __restrict__ bias,
                     float* __restrict__ Cout,
                     int M) {
    extern __shared__ __half smh[];
    const uint32_t sb = smem_u32(smh);
    const int tid  = threadIdx.x;
    const int lane = tid & 31;
    const int wid  = tid >> 5;
    const int gid  = lane >> 2;      // 0..7
    const int tig  = lane & 3;       // 0..3
    const int wr   = wid >> 2;       // 0..1  (64-row band)
    const int wc   = wid & 3;        // 0..3  (64-col band)
    const int z    = blockIdx.z;

    const __half* __restrict__ Bmat = WT5 + (size_t)z * DD * DD;
    float* __restrict__ C = (z == 0) ? Cout : (g_H + (size_t)(z - 1) * NN * DD);

    const int row0 = blockIdx.y * BM;
    const int col0 = blockIdx.x * BN;

    float acc[4][8][4];
    #pragma unroll
    for (int mt = 0; mt < 4; mt++)
        #pragma unroll
        for (int nt = 0; nt < 8; nt++)
            #pragma unroll
            for (int q = 0; q < 4; q++) acc[mt][nt][q] = 0.0f;

    // ---- async stage fill: A 512 b128 slots, B 1024 b128 slots ----
    #define LOAD_CHUNK(c)                                                     \
    do {                                                                      \
        const int _stg = (c) % STG;                                           \
        const int _k0  = (c) * BK;                                            \
        const uint32_t _ab = sb + _stg * (ASZB + BSZB);                       \
        const uint32_t _bb = _ab + ASZB;                                      \
        _Pragma("unroll")                                                     \
        for (int _j = 0; _j < 2; _j++) {                                      \
            int _s = tid + 256 * _j, _r = _s >> 2, _c8 = _s & 3;              \
            int _ar = row0 + _r; if (_ar >= M) _ar = M - 1;                   \
            cp_async16(_ab + _r * (PADH * 2) + _c8 * 16,                      \
                       Ain + (size_t)_ar * DD + _k0 + _c8 * 8);               \
        }                                                                     \
        _Pragma("unroll")                                                     \
        for (int _j = 0; _j < 4; _j++) {                                      \
            int _s = tid + 256 * _j, _r = _s >> 2, _c8 = _s & 3;              \
            cp_async16(_bb + _r * (PADH * 2) + _c8 * 16,                      \
                       Bmat + (size_t)(col0 + _r) * DD + _k0 + _c8 * 8);      \
        }                                                                     \
        CP_COMMIT();                                                          \
    } while (0)

    LOAD_CHUNK(0);
    LOAD_CHUNK(1);
    for (int c = 0; c < 24; c++) {
        if (c + 2 < 24) LOAD_CHUNK(c + 2);
        if (c < 22)      CP_WAIT(2);
        else if (c == 22) CP_WAIT(1);
        else              CP_WAIT(0);
        __syncthreads();

        const int stg = c % STG;
        const __half* __restrict__ as = smh + stg * (ASZB + BSZB) / 2;
        const __half* __restrict__ bs = as + ASZB / 2;

        #pragma unroll
        for (int ks = 0; ks < 2; ks++) {           // two K=16 steps per chunk
            const int kk = ks * 16 + tig * 2;
            uint32_t af[4][4], bf[8][2];
            #pragma unroll
            for (int mt = 0; mt < 4; mt++) {
                int r = wr * 64 + mt * 16 + gid;
                af[mt][0] = *reinterpret_cast<const uint32_t*>(&as[r * PADH + kk]);
                af[mt][1] = *reinterpret_cast<const uint32_t*>(&as[(r + 8) * PADH + kk]);
                af[mt][2] = *reinterpret_cast<const uint32_t*>(&as[r * PADH + kk + 8]);
                af[mt][3] = *reinterpret_cast<const uint32_t*>(&as[(r + 8) * PADH + kk + 8]);
            }
            #pragma unroll
            for (int nt = 0; nt < 8; nt++) {
                int n = wc * 64 + nt * 8 + gid;
                bf[nt][0] = *reinterpret_cast<const uint32_t*>(&bs[n * PADH + kk]);
                bf[nt][1] = *reinterpret_cast<const uint32_t*>(&bs[n * PADH + kk + 8]);
            }
            #pragma unroll
            for (int mt = 0; mt < 4; mt++)
                #pragma unroll
                for (int nt = 0; nt < 8; nt++)
                    mma16n8k16(acc[mt][nt], af[mt], bf[nt]);
        }
        __syncthreads();
    }

    // ---- epilogue (C frag: c0,c1 row gid cols 2tig..; c2,c3 row gid+8) ----
    #pragma unroll
    for (int mt = 0; mt < 4; mt++) {
        const int r0g = row0 + wr * 64 + mt * 16 + gid;
        #pragma unroll
        for (int nt = 0; nt < 8; nt++) {
            const int col = col0 + wc * 64 + nt * 8 + 2 * tig;
            float bx = 0.f, by = 0.f;
            if (z == 0) { bx = bias[col]; by = bias[col + 1]; }
            if (r0g < M) {
                float2 v = make_float2(acc[mt][nt][0] + bx, acc[mt][nt][1] + by);
                *reinterpret_cast<float2*>(C + (size_t)r0g * DD + col) = v;
            }
            if (r0g + 8 < M) {
                float2 v = make_float2(acc[mt][nt][2] + bx, acc[mt][nt][3] + by);
                *reinterpret_cast<float2*>(C + (size_t)(r0g + 8) * DD + col) = v;
            }
        }
    }
}

// ---------------------------------------------------------------------------
// Edge scatter (validated): out[dst] += g_H[etype][src] * norm[e]
// ---------------------------------------------------------------------------
__global__ void scatter_kernel(float* __restrict__ out) {
    const int e = blockIdx.x;
    const int s = g_src[e];
    const int d = g_dst[e];
    const int r = g_et[e];
    const float w = g_norm[e];
    const float* __restrict__ h = g_H + ((size_t)r * NN + s) * DD;
    float* __restrict__ o = out + (size_t)d * DD;
    for (int j = threadIdx.x; j < DD; j += blockDim.x)
        atomicAdd(o + j, h[j] * w);
}

// ---------------------------------------------------------------------------
// Orchestration
// ---------------------------------------------------------------------------
extern "C" void kernel_launch(void* const* d_in, const int* in_sizes, int n_in,
                              void* d_out, int out_size) {
    const float* entity = (const float*)d_in[0];
    const void*  eidx   = d_in[1];
    const void*  etype  = d_in[2];
    const float* W1 = (const float*)d_in[3];
    const float* r1 = (const float*)d_in[4];
    const float* b1 = (const float*)d_in[5];
    const float* W2 = (const float*)d_in[6];
    const float* r2 = (const float*)d_in[7];
    const float* b2 = (const float*)d_in[8];
    const float* W3 = (const float*)d_in[9];
    const float* r3 = (const float*)d_in[10];
    const float* b3 = (const float*)d_in[11];

    float  *XA = nullptr, *XB = nullptr;
    __half *AH = nullptr, *WTH = nullptr;
    cudaGetSymbolAddress((void**)&XA,  g_XA);
    cudaGetSymbolAddress((void**)&XB,  g_XB);
    cudaGetSymbolAddress((void**)&AH,  g_Ah);
    cudaGetSymbolAddress((void**)&WTH, g_WTh);
    float* OUT = (float*)d_out;

    cudaFuncSetAttribute(gemm_mma_kernel,
                         cudaFuncAttributeMaxDynamicSharedMemorySize, SMTOT);

    const dim3 tr_grid(24, 24, 15), tr_blk(32, 8);
    const dim3 gemm_grid(DD / BN, (NN + BM - 1) / BM, NR + 1);   // (3, 157, 5)
    const int  vec_grid = (int)(((size_t)NN * DD / 4 + 255) / 256);
    const size_t WTL = (size_t)5 * DD * DD;

    transpose_all_kernel<<<tr_grid, tr_blk>>>(W1, r1, W2, r2, W3, r3);
    convert_entity_kernel<<<vec_grid, 256>>>(entity);
    detect_dtype_kernel<<<1, 256>>>((const int*)eidx);
    canon_idx_kernel<<<(NE + 255) / 256, 256>>>(eidx, etype);
    zero_deg_kernel<<<(NR * NN + 255) / 256, 256>>>();

    // --- layer 1: f16(entity) -> XA ---
    gemm_mma_kernel<<<gemm_grid, 256, SMTOT>>>(AH, WTH + 0 * WTL, b1, XA, NN);
    count_deg_kernel<<<(NE + 255) / 256, 256>>>();
    compute_norm_kernel<<<(NE + 255) / 256, 256>>>();
    scatter_kernel<<<NE, 256>>>(XA);
    relu_to_half_kernel<<<vec_grid, 256>>>(XA);

    // --- layer 2: f16(relu(XA)) -> XB ---
    gemm_mma_kernel<<<gemm_grid, 256, SMTOT>>>(AH, WTH + 1 * WTL, b2, XB, NN);
    scatter_kernel<<<NE, 256>>>(XB);
    relu_to_half_kernel<<<vec_grid, 256>>>(XB);

    // --- layer 3: f16(relu(XB)) -> d_out (no ReLU) ---
    gemm_mma_kernel<<<gemm_grid, 256, SMTOT>>>(AH, WTH + 2 * WTL, b3, OUT, NN);
    scatter_kernel<<<NE, 256>>>(OUT);
}

// round 13
// speedup vs baseline: 4.4090x; 1.0096x over previous
#include <cuda_runtime.h>
#include <cuda_fp16.h>
#include <cstdint>

// Problem constants (fixed by the reference).
#define NN 20000      // nodes
#define NE 100000     // edges
#define DD 768        // feature dim
#define NR 4          // relations

// ---------------------------------------------------------------------------
// Device scratch (no allocations allowed anywhere).
// ---------------------------------------------------------------------------
__device__ float  g_H[(size_t)NR * NN * DD];     // per-relation transformed nodes
__device__ float  g_XA[(size_t)NN * DD];         // layer ping buffer (fp32)
__device__ float  g_XB[(size_t)NN * DD];         // layer pong buffer (fp32)
__device__ __half g_Ah[(size_t)NN * DD];         // fp16 GEMM A operand (current layer)
__device__ __half g_WTh[(size_t)15 * DD * DD];   // transposed fp16 weights [l*5+s][N][K]
__device__ float  g_deg[NR * NN];                // per (relation,dst) in-degree
__device__ float  g_norm[NE];                    // per-edge mean weight
__device__ int    g_src[NE];
__device__ int    g_dst[NE];
__device__ int    g_et[NE];
__device__ int    g_is64;

// ---------------------------------------------------------------------------
// Helpers (base-PTX only: cp.async sm_80, mma.sync fp16 — OK on sm_100 target)
// ---------------------------------------------------------------------------
__device__ __forceinline__ uint32_t smem_u32(const void* p) {
    uint32_t a;
    asm("{ .reg .u64 t; cvta.to.shared.u64 t, %1; cvt.u32.u64 %0, t; }"
        : "=r"(a) : "l"(p));
    return a;
}
__device__ __forceinline__ void cp_async16(uint32_t dst, const void* src) {
    asm volatile("cp.async.cg.shared.global [%0], [%1], 16;\n"
                 :: "r"(dst), "l"(src));
}
#define CP_COMMIT()  asm volatile("cp.async.commit_group;\n" ::: "memory")
#define CP_WAIT(n)   asm volatile("cp.async.wait_group %0;\n" :: "n"(n) : "memory")

// D += A(16x16 f16,row) * B(16x8 f16,col); fp32 accum.
__device__ __forceinline__ void mma16n8k16(float* c, const uint32_t* a,
                                           const uint32_t* b) {
    asm volatile(
        "mma.sync.aligned.m16n8k16.row.col.f32.f16.f16.f32 "
        "{%0,%1,%2,%3}, {%4,%5,%6,%7}, {%8,%9}, {%0,%1,%2,%3};"
        : "+f"(c[0]), "+f"(c[1]), "+f"(c[2]), "+f"(c[3])
        : "r"(a[0]), "r"(a[1]), "r"(a[2]), "r"(a[3]), "r"(b[0]), "r"(b[1]));
}

// ---------------------------------------------------------------------------
// Index dtype detection + canonicalization (validated in R4).
// ---------------------------------------------------------------------------
__global__ void detect_dtype_kernel(const int* __restrict__ eidx_raw) {
    __shared__ int s_or[256];
    int acc = 0;
    for (int i = threadIdx.x; i < 2048; i += 256)
        acc |= eidx_raw[2 * i + 1];
    s_or[threadIdx.x] = acc;
    __syncthreads();
    for (int s = 128; s > 0; s >>= 1) {
        if (threadIdx.x < s) s_or[threadIdx.x] |= s_or[threadIdx.x + s];
        __syncthreads();
    }
    if (threadIdx.x == 0) g_is64 = (s_or[0] == 0) ? 1 : 0;
}

__global__ void canon_idx_kernel(const void* __restrict__ eidx_raw,
                                 const void* __restrict__ etype_raw) {
    int e = blockIdx.x * blockDim.x + threadIdx.x;
    if (e >= NE) return;
    if (g_is64) {
        const long long* ei = (const long long*)eidx_raw;
        const long long* et = (const long long*)etype_raw;
        g_src[e] = (int)ei[e];
        g_dst[e] = (int)ei[NE + e];
        g_et[e]  = (int)et[e];
    } else {
        const int* ei = (const int*)eidx_raw;
        const int* et = (const int*)etype_raw;
        g_src[e] = ei[e];
        g_dst[e] = ei[NE + e];
        g_et[e]  = et[e];
    }
}

__global__ void zero_deg_kernel() {
    int i = blockIdx.x * blockDim.x + threadIdx.x;
    if (i < NR * NN) g_deg[i] = 0.0f;
}
__global__ void count_deg_kernel() {
    int e = blockIdx.x * blockDim.x + threadIdx.x;
    if (e < NE) atomicAdd(&g_deg[g_et[e] * NN + g_dst[e]], 1.0f);
}
__global__ void compute_norm_kernel() {
    int e = blockIdx.x * blockDim.x + threadIdx.x;
    if (e < NE) g_norm[e] = 1.0f / fmaxf(g_deg[g_et[e] * NN + g_dst[e]], 1.0f);
}

// ---------------------------------------------------------------------------
// Weight transpose (all 15 mats), fp16 on store.
// slot 0 = root^T, 1..4 = W[r]^T ; dst[n][k] = f16(src[k][n]).
// ---------------------------------------------------------------------------
__global__ void transpose_all_kernel(const float* __restrict__ W1, const float* __restrict__ r1,
                                     const float* __restrict__ W2, const float* __restrict__ r2,
                                     const float* __restrict__ W3, const float* __restrict__ r3) {
    __shared__ float t[32][33];
    const int zz = blockIdx.z;
    const int layer = zz / 5, slot = zz % 5;
    const float* roots[3] = {r1, r2, r3};
    const float* Ws[3]    = {W1, W2, W3};
    const float* src = (slot == 0) ? roots[layer]
                                   : Ws[layer] + (size_t)(slot - 1) * DD * DD;
    __half* dst = g_WTh + (size_t)zz * DD * DD;

    int x  = blockIdx.x * 32 + threadIdx.x;
    int y0 = blockIdx.y * 32;
    for (int j = threadIdx.y; j < 32; j += 8)
        t[j][threadIdx.x] = src[(size_t)(y0 + j) * DD + x];
    __syncthreads();
    int x2  = blockIdx.y * 32 + threadIdx.x;
    int y20 = blockIdx.x * 32;
    for (int j = threadIdx.y; j < 32; j += 8)
        dst[(size_t)(y20 + j) * DD + x2] = __float2half_rn(t[threadIdx.x][j]);
}

// Entity -> fp16 copy (GEMM A operand for layer 1).
__global__ void convert_entity_kernel(const float* __restrict__ x) {
    const size_t n4 = (size_t)NN * DD / 4;
    size_t i = (size_t)blockIdx.x * blockDim.x + threadIdx.x;
    if (i < n4) {
        float4 v = reinterpret_cast<const float4*>(x)[i];
        __half2* o = reinterpret_cast<__half2*>(g_Ah) + i * 2;
        o[0] = __floats2half2_rn(v.x, v.y);
        o[1] = __floats2half2_rn(v.z, v.w);
    }
}

// ReLU fp32 -> fp16 operand (X only feeds the next GEMM; scatter reads g_H).
__global__ void relu_to_half_kernel(const float* __restrict__ x) {
    const size_t n4 = (size_t)NN * DD / 4;
    size_t i = (size_t)blockIdx.x * blockDim.x + threadIdx.x;
    if (i < n4) {
        float4 v = reinterpret_cast<const float4*>(x)[i];
        v.x = fmaxf(v.x, 0.f); v.y = fmaxf(v.y, 0.f);
        v.z = fmaxf(v.z, 0.f); v.w = fmaxf(v.w, 0.f);
        __half2* o = reinterpret_cast<__half2*>(g_Ah) + i * 2;
        o[0] = __floats2half2_rn(v.x, v.y);
        o[1] = __floats2half2_rn(v.z, v.w);
    }
}

// ---------------------------------------------------------------------------
// fp16 mma.sync GEMM (m16n8k16), fp32 accumulate.
// CTA 128x256 out, BK=32, 256 thr (8 warps), warp tile 64x64, 3-stage cp.async.
//   blockIdx.z = slot (0 -> root+bias into Cout, 1..4 -> g_H[slot-1]).
// SMEM rows padded to 40 halfs: frag b32 bank = (gid*20+tig)%32, conflict-free.
// ---------------------------------------------------------------------------
#define BM   128
#define BN   256
#define BK   32
#define PADH 40
#define ASZB (BM * PADH * 2)                 // 10240 B per A stage
#define BSZB (BN * PADH * 2)                 // 20480 B per B stage
#define STG  3
#define SMTOT (STG * (ASZB + BSZB))          // 92160 B

__global__ __launch_bounds__(256, 1)
void gemm_mma_kernel(const __half* __restrict__ Ain,
                     const __half* __restrict__ WT5,   // 5 transposed [N][K] mats
                     const float* __restrict__ bias,
                     float* __restrict__ Cout,
                     int M) {
    extern __shared__ __half smh[];
    const uint32_t sb = smem_u32(smh);
    const int tid  = threadIdx.x;
    const int lane = tid & 31;
    const int wid  = tid >> 5;
    const int gid  = lane >> 2;      // 0..7
    const int tig  = lane & 3;       // 0..3
    const int wr   = wid >> 2;       // 0..1  (64-row band)
    const int wc   = wid & 3;        // 0..3  (64-col band)
    const int z    = blockIdx.z;

    const __half* __restrict__ Bmat = WT5 + (size_t)z * DD * DD;
    float* __restrict__ C = (z == 0) ? Cout : (g_H + (size_t)(z - 1) * NN * DD);

    const int row0 = blockIdx.y * BM;
    const int col0 = blockIdx.x * BN;

    float acc[4][8][4];
    #pragma unroll
    for (int mt = 0; mt < 4; mt++)
        #pragma unroll
        for (int nt = 0; nt < 8; nt++)
            #pragma unroll
            for (int q = 0; q < 4; q++) acc[mt][nt][q] = 0.0f;

    // ---- async stage fill: A 512 b128 slots, B 1024 b128 slots ----
    #define LOAD_CHUNK(c)                                                     \
    do {                                                                      \
        const int _stg = (c) % STG;                                           \
        const int _k0  = (c) * BK;                                            \
        const uint32_t _ab = sb + _stg * (ASZB + BSZB);                       \
        const uint32_t _bb = _ab + ASZB;                                      \
        _Pragma("unroll")                                                     \
        for (int _j = 0; _j < 2; _j++) {                                      \
            int _s = tid + 256 * _j, _r = _s >> 2, _c8 = _s & 3;              \
            int _ar = row0 + _r; if (_ar >= M) _ar = M - 1;                   \
            cp_async16(_ab + _r * (PADH * 2) + _c8 * 16,                      \
                       Ain + (size_t)_ar * DD + _k0 + _c8 * 8);               \
        }                                                                     \
        _Pragma("unroll")                                                     \
        for (int _j = 0; _j < 4; _j++) {                                      \
            int _s = tid + 256 * _j, _r = _s >> 2, _c8 = _s & 3;              \
            cp_async16(_bb + _r * (PADH * 2) + _c8 * 16,                      \
                       Bmat + (size_t)(col0 + _r) * DD + _k0 + _c8 * 8);      \
        }                                                                     \
        CP_COMMIT();                                                          \
    } while (0)

    LOAD_CHUNK(0);
    LOAD_CHUNK(1);
    for (int c = 0; c < 24; c++) {
        if (c + 2 < 24) LOAD_CHUNK(c + 2);
        if (c < 22)      CP_WAIT(2);
        else if (c == 22) CP_WAIT(1);
        else              CP_WAIT(0);
        __syncthreads();

        const int stg = c % STG;
        const __half* __restrict__ as = smh + stg * (ASZB + BSZB) / 2;
        const __half* __restrict__ bs = as + ASZB / 2;

        #pragma unroll
        for (int ks = 0; ks < 2; ks++) {           // two K=16 steps per chunk
            const int kk = ks * 16 + tig * 2;
            uint32_t af[4][4], bf[8][2];
            #pragma unroll
            for (int mt = 0; mt < 4; mt++) {
                int r = wr * 64 + mt * 16 + gid;
                af[mt][0] = *reinterpret_cast<const uint32_t*>(&as[r * PADH + kk]);
                af[mt][1] = *reinterpret_cast<const uint32_t*>(&as[(r + 8) * PADH + kk]);
                af[mt][2] = *reinterpret_cast<const uint32_t*>(&as[r * PADH + kk + 8]);
                af[mt][3] = *reinterpret_cast<const uint32_t*>(&as[(r + 8) * PADH + kk + 8]);
            }
            #pragma unroll
            for (int nt = 0; nt < 8; nt++) {
                int n = wc * 64 + nt * 8 + gid;
                bf[nt][0] = *reinterpret_cast<const uint32_t*>(&bs[n * PADH + kk]);
                bf[nt][1] = *reinterpret_cast<const uint32_t*>(&bs[n * PADH + kk + 8]);
            }
            #pragma unroll
            for (int mt = 0; mt < 4; mt++)
                #pragma unroll
                for (int nt = 0; nt < 8; nt++)
                    mma16n8k16(acc[mt][nt], af[mt], bf[nt]);
        }
        __syncthreads();
    }

    // ---- epilogue (C frag: c0,c1 row gid cols 2tig..; c2,c3 row gid+8) ----
    #pragma unroll
    for (int mt = 0; mt < 4; mt++) {
        const int r0g = row0 + wr * 64 + mt * 16 + gid;
        #pragma unroll
        for (int nt = 0; nt < 8; nt++) {
            const int col = col0 + wc * 64 + nt * 8 + 2 * tig;
            float bx = 0.f, by = 0.f;
            if (z == 0) { bx = bias[col]; by = bias[col + 1]; }
            if (r0g < M) {
                float2 v = make_float2(acc[mt][nt][0] + bx, acc[mt][nt][1] + by);
                *reinterpret_cast<float2*>(C + (size_t)r0g * DD + col) = v;
            }
            if (r0g + 8 < M) {
                float2 v = make_float2(acc[mt][nt][2] + bx, acc[mt][nt][3] + by);
                *reinterpret_cast<float2*>(C + (size_t)(r0g + 8) * DD + col) = v;
            }
        }
    }
}

// ---------------------------------------------------------------------------
// Edge scatter (validated): out[dst] += g_H[etype][src] * norm[e]
// ---------------------------------------------------------------------------
__global__ void scatter_kernel(float* __restrict__ out) {
    const int e = blockIdx.x;
    const int s = g_src[e];
    const int d = g_dst[e];
    const int r = g_et[e];
    const float w = g_norm[e];
    const float* __restrict__ h = g_H + ((size_t)r * NN + s) * DD;
    float* __restrict__ o = out + (size_t)d * DD;
    for (int j = threadIdx.x; j < DD; j += blockDim.x)
        atomicAdd(o + j, h[j] * w);
}

// ---------------------------------------------------------------------------
// Orchestration
// ---------------------------------------------------------------------------
extern "C" void kernel_launch(void* const* d_in, const int* in_sizes, int n_in,
                              void* d_out, int out_size) {
    const float* entity = (const float*)d_in[0];
    const void*  eidx   = d_in[1];
    const void*  etype  = d_in[2];
    const float* W1 = (const float*)d_in[3];
    const float* r1 = (const float*)d_in[4];
    const float* b1 = (const float*)d_in[5];
    const float* W2 = (const float*)d_in[6];
    const float* r2 = (const float*)d_in[7];
    const float* b2 = (const float*)d_in[8];
    const float* W3 = (const float*)d_in[9];
    const float* r3 = (const float*)d_in[10];
    const float* b3 = (const float*)d_in[11];

    float  *XA = nullptr, *XB = nullptr;
    __half *AH = nullptr, *WTH = nullptr;
    cudaGetSymbolAddress((void**)&XA,  g_XA);
    cudaGetSymbolAddress((void**)&XB,  g_XB);
    cudaGetSymbolAddress((void**)&AH,  g_Ah);
    cudaGetSymbolAddress((void**)&WTH, g_WTh);
    float* OUT = (float*)d_out;

    cudaFuncSetAttribute(gemm_mma_kernel,
                         cudaFuncAttributeMaxDynamicSharedMemorySize, SMTOT);

    const dim3 tr_grid(24, 24, 15), tr_blk(32, 8);
    const dim3 gemm_grid(DD / BN, (NN + BM - 1) / BM, NR + 1);   // (3, 157, 5)
    const int  vec_grid = (int)(((size_t)NN * DD / 4 + 255) / 256);
    const size_t WTL = (size_t)5 * DD * DD;

    transpose_all_kernel<<<tr_grid, tr_blk>>>(W1, r1, W2, r2, W3, r3);
    convert_entity_kernel<<<vec_grid, 256>>>(entity);
    detect_dtype_kernel<<<1, 256>>>((const int*)eidx);
    canon_idx_kernel<<<(NE + 255) / 256, 256>>>(eidx, etype);
    zero_deg_kernel<<<(NR * NN + 255) / 256, 256>>>();

    // --- layer 1: f16(entity) -> XA ---
    gemm_mma_kernel<<<gemm_grid, 256, SMTOT>>>(AH, WTH + 0 * WTL, b1, XA, NN);
    count_deg_kernel<<<(NE + 255) / 256, 256>>>();
    compute_norm_kernel<<<(NE + 255) / 256, 256>>>();
    scatter_kernel<<<NE, 256>>>(XA);
    relu_to_half_kernel<<<vec_grid, 256>>>(XA);

    // --- layer 2: f16(relu(XA)) -> XB ---
    gemm_mma_kernel<<<gemm_grid, 256, SMTOT>>>(AH, WTH + 1 * WTL, b2, XB, NN);
    scatter_kernel<<<NE, 256>>>(XB);
    relu_to_half_kernel<<<vec_grid, 256>>>(XB);

    // --- layer 3: f16(relu(XB)) -> d_out (no ReLU) ---
    gemm_mma_kernel<<<gemm_grid, 256, SMTOT>>>(AH, WTH + 2 * WTL, b3, OUT, NN);
    scatter_kernel<<<NE, 256>>>(OUT);
}